// round 9
// baseline (speedup 1.0000x reference)
#include <cuda_runtime.h>
#include <cuda.h>
#include <math.h>
#include <stdint.h>

// YOLO loss: preds [16384,7,7,30] f32, labels same, scalar f32 out.
// Persistent cp.async double-buffered pipeline (R4 mechanics), upgraded:
//   592 blocks (148 SM x 4) x 128 threads; 7168 chunks of 112 cells.
//   smem 53.76 KB/CTA -> 4 CTAs/SM. While computing chunk c from buffer A,
//   chunk c+592 streams into buffer B (cp.async.cg 16B, wait_group 1).
//   Compute: float2 reads + noobj fast path (3 scalar loads, ~70% of cells).
//   Block reduce + ticket atomic; last block reduces 592 partials in double.

#define SIDE 7
#define NBATCH 16384
#define NTHREADS 128
#define TILE_CELLS 112
#define NUM_CHUNKS 7168            // 802816 / 112 exactly
#define PGRID 592                  // 148 * 4 persistent blocks
#define TILE_FLOATS (TILE_CELLS * 30)        // 3360
#define TILE4 (TILE_FLOATS / 4)              // 840 float4 per array
#define TILE_BYTES (TILE_FLOATS * 4)         // 13440 B per array
#define STAGE4 (2 * TILE4)                   // 1680 float4 (preds|labels)
#define STAGE_BYTES (2 * TILE_BYTES)         // 26880 B
#define SMEM_BYTES (2 * STAGE_BYTES)         // 53760 B (2 stages)

__device__ float g_partials[PGRID];
__device__ unsigned int g_ticket = 0;

__device__ __forceinline__ void cp16(uint32_t smem_addr, const float4* gptr) {
    asm volatile("cp.async.cg.shared.global [%0], [%1], 16;\n"
                 :: "r"(smem_addr), "l"(gptr));
}

// Stage one chunk (840 float4 preds + 840 labels) into stage `sbase`.
__device__ __forceinline__ void prefetch_chunk(uint32_t sbase,
                                               const float4* __restrict__ p4,
                                               const float4* __restrict__ l4,
                                               int chunk, int t)
{
    const long long b = (long long)chunk * TILE4;
    const float4* ps = p4 + b;
    const float4* ls = l4 + b;
    #pragma unroll
    for (int j = 0; j < 6; j++) {            // 6*128 = 768
        int i = t + j * NTHREADS;
        cp16(sbase + (uint32_t)i * 16u, ps + i);
        cp16(sbase + (uint32_t)(TILE4 + i) * 16u, ls + i);
    }
    if (t < TILE4 - 6 * NTHREADS) {           // tail: 72 float4 each
        int i = t + 6 * NTHREADS;
        cp16(sbase + (uint32_t)i * 16u, ps + i);
        cp16(sbase + (uint32_t)(TILE4 + i) * 16u, ls + i);
    }
}

__device__ __forceinline__ float cell_loss(const float* __restrict__ p,
                                           const float* __restrict__ l)
{
    const float s = 1.0f / (float)SIDE;
    float lconf = l[4];
    if (lconf == 0.0f) {
        // noobj: labels conf (indices 4 and 9) both zero here
        float d0 = p[4];
        float d1 = p[9];
        return 0.5f * (d0 * d0 + d1 * d1);
    }

    // 8B-aligned (cell stride 120 B): read via float2.
    const float2* p2 = (const float2*)p;
    const float2* l2 = (const float2*)l;

    float2 pa01 = p2[0], pa23 = p2[1], pa45 = p2[2], pa67 = p2[3], pa89 = p2[4];
    float2 la01 = l2[0], la23 = l2[1], la45 = l2[2], la67 = l2[3], la89 = l2[4];

    // IoU target: label box 0 only (lbox = lb[..., 0:1, :])
    float l1x = la01.x * s - 0.5f * la23.x;
    float l1y = la01.y * s - 0.5f * la23.y;
    float l2x = la01.x * s + 0.5f * la23.x;
    float l2y = la01.y * s + 0.5f * la23.y;
    float la  = la23.x * la23.y;

    // pred boxes: b0 = {pa01.x, pa01.y, pa23.x, pa23.y, pa45.x}
    //             b1 = {pa45.y, pa67.x, pa67.y, pa89.x, pa89.y}
    float bx[2] = { pa01.x, pa45.y };
    float by[2] = { pa01.y, pa67.x };
    float bw[2] = { pa23.x, pa67.y };
    float bh[2] = { pa23.y, pa89.x };
    float bc[2] = { pa45.x, pa89.y };

    // label boxes, same layout
    float lx[2] = { la01.x, la45.y };
    float ly[2] = { la01.y, la67.x };
    float lw[2] = { la23.x, la67.y };
    float lh[2] = { la23.y, la89.x };

    float iou[2];
    #pragma unroll
    for (int b = 0; b < 2; b++) {
        float p1x = bx[b] * s - 0.5f * bw[b];
        float p1y = by[b] * s - 0.5f * bh[b];
        float p2x = bx[b] * s + 0.5f * bw[b];
        float p2y = by[b] * s + 0.5f * bh[b];
        float iw = fmaxf(fminf(p2x, l2x) - fmaxf(p1x, l1x), 0.0f);
        float ih = fmaxf(fminf(p2y, l2y) - fmaxf(p1y, l1y), 0.0f);
        float inter = iw * ih;
        float pa = bw[b] * bh[b];
        iou[b] = inter / (pa + la - inter);
    }

    int idx = (iou[1] > iou[0]) ? 1 : 0;   // jnp.argmax: first max wins
    float maxiou = fmaxf(iou[0], iou[1]);

    float dresp = bc[idx] - maxiou;
    float resp  = dresp * dresp;

    float nrc = bc[1 - idx];
    float nr  = nrc * nrc;

    // responsible losses: pred box idx vs LABEL box idx (lr = take(lb))
    float dx = bx[idx] - lx[idx];
    float dy = by[idx] - ly[idx];
    float xy = dx * dx + dy * dy;

    float dw = sqrtf(bw[idx]) - sqrtf(lw[idx]);
    float dh = sqrtf(bh[idx]) - sqrtf(lh[idx]);
    float wh = dw * dw + dh * dh;

    float cls = 0.0f;
    #pragma unroll
    for (int j = 5; j < 15; j++) {
        float2 a = p2[j];
        float2 b = l2[j];
        float d0 = a.x - b.x;
        float d1 = a.y - b.y;
        cls += d0 * d0 + d1 * d1;
    }

    return 5.0f * (xy + wh) + 2.0f * resp + nr + cls;
}

extern __shared__ float4 smem4[];   // [2 stages][preds 840 | labels 840] float4

__global__ __launch_bounds__(NTHREADS)
void yolo_pipe2_kernel(const float* __restrict__ preds,
                       const float* __restrict__ labels,
                       float* __restrict__ out)
{
    const int t = threadIdx.x;
    const float4* p4 = (const float4*)preds;
    const float4* l4 = (const float4*)labels;

    const uint32_t sbase = (uint32_t)__cvta_generic_to_shared(smem4);

    float acc_cell = 0.0f;

    int c = blockIdx.x;
    int buf = 0;

    // Prologue: prefetch first chunk into stage 0.
    prefetch_chunk(sbase, p4, l4, c, t);
    asm volatile("cp.async.commit_group;\n" ::: "memory");

    while (c < NUM_CHUNKS) {
        int cn = c + PGRID;
        if (cn < NUM_CHUNKS)
            prefetch_chunk(sbase + (uint32_t)(buf ^ 1) * STAGE_BYTES, p4, l4, cn, t);
        asm volatile("cp.async.commit_group;\n" ::: "memory");

        // All groups except the newest are done -> current stage ready.
        asm volatile("cp.async.wait_group 1;\n" ::: "memory");
        __syncthreads();

        if (t < TILE_CELLS) {
            const float* sp = (const float*)(smem4 + (size_t)buf * (STAGE4));
            const float* sl = sp + TILE_FLOATS;
            acc_cell += cell_loss(sp + t * 30, sl + t * 30);
        }

        __syncthreads();   // all reads done before this stage is refilled
        buf ^= 1;
        c = cn;
    }

    // Block reduction: warp shuffle tree then cross-warp via smem.
    float v = acc_cell;
    #pragma unroll
    for (int off = 16; off > 0; off >>= 1)
        v += __shfl_down_sync(0xFFFFFFFFu, v, off);

    __shared__ float wsum[NTHREADS / 32];
    int lane = t & 31;
    int wid  = t >> 5;
    if (lane == 0) wsum[wid] = v;
    __syncthreads();

    __shared__ bool is_last;
    if (t == 0) {
        float bacc = 0.0f;
        #pragma unroll
        for (int w = 0; w < NTHREADS / 32; w++) bacc += wsum[w];
        g_partials[blockIdx.x] = bacc;
        __threadfence();
        unsigned int ticket = atomicAdd(&g_ticket, 1u);
        is_last = (ticket == PGRID - 1);
    }
    __syncthreads();

    // Last-arriving block: deterministic final reduction over 592 partials.
    if (is_last) {
        double acc = 0.0;
        #pragma unroll 1
        for (int i = t; i < PGRID; i += NTHREADS)
            acc += (double)g_partials[i];

        #pragma unroll
        for (int off = 16; off > 0; off >>= 1)
            acc += __shfl_down_sync(0xFFFFFFFFu, acc, off);

        __shared__ double dsum[NTHREADS / 32];
        if (lane == 0) dsum[wid] = acc;
        __syncthreads();

        if (t == 0) {
            double total = 0.0;
            #pragma unroll
            for (int w = 0; w < NTHREADS / 32; w++) total += dsum[w];
            out[0] = (float)(total / (double)NBATCH);
            g_ticket = 0;   // reset for next graph replay
        }
    }
}

extern "C" void kernel_launch(void* const* d_in, const int* in_sizes, int n_in,
                              void* d_out, int out_size)
{
    const float* preds  = (const float*)d_in[0];
    const float* labels = (const float*)d_in[1];
    float* out = (float*)d_out;

    static bool attr_set = false;
    if (!attr_set) {
        cudaFuncSetAttribute(yolo_pipe2_kernel,
                             cudaFuncAttributeMaxDynamicSharedMemorySize,
                             SMEM_BYTES);
        attr_set = true;
    }

    yolo_pipe2_kernel<<<PGRID, NTHREADS, SMEM_BYTES>>>(preds, labels, out);
}

// round 10
// speedup vs baseline: 1.3367x; 1.3367x over previous
#include <cuda_runtime.h>
#include <cuda.h>
#include <math.h>
#include <stdint.h>

// YOLO loss: preds [16384,7,7,30] f32, labels same, scalar f32 out.
// R10 = R4 skeleton EXACTLY (444 blocks x 128 threads, 128-cell chunks,
// cp.async.cg 16B double-buffer, wait_group 1), with ONE change:
// cell_loss uses float2 smem reads + noobj fast path.

#define SIDE 7
#define NBATCH 16384
#define CELLS_PER_BLOCK 128
#define NUM_CHUNKS 6272            // 802816 / 128 exactly
#define PGRID 444                  // 148 * 3 persistent blocks
#define FLOATS_PER_CELL 30
#define CHUNKF (CELLS_PER_BLOCK * FLOATS_PER_CELL)   // 3840 floats
#define CHUNK4 (CHUNKF / 4)                          // 960 float4 per array
#define BUF4 (2 * CHUNK4)                            // 1920 float4 per buffer
#define SMEM_BYTES (2 * BUF4 * 16)                   // 61440 B

__device__ float g_partials[PGRID];
__device__ unsigned int g_ticket = 0;

__device__ __forceinline__ void cp16(uint32_t smem_addr, const float4* gptr) {
    asm volatile("cp.async.cg.shared.global [%0], [%1], 16;\n"
                 :: "r"(smem_addr), "l"(gptr));
}

// Stage one chunk (960 float4 of preds + 960 of labels) into buffer `sbase`.
__device__ __forceinline__ void prefetch_chunk(uint32_t sbase,
                                               const float4* __restrict__ p4,
                                               const float4* __restrict__ l4,
                                               int chunk, int t)
{
    const long long b = (long long)chunk * CHUNK4;
    const float4* ps = p4 + b;
    const float4* ls = l4 + b;
    #pragma unroll
    for (int j = 0; j < 7; j++) {
        int i = t + j * CELLS_PER_BLOCK;
        cp16(sbase + (uint32_t)i * 16u, ps + i);
        cp16(sbase + (uint32_t)(CHUNK4 + i) * 16u, ls + i);
    }
    if (t < CHUNK4 - 7 * CELLS_PER_BLOCK) {   // tail: 64 float4 each
        int i = t + 7 * CELLS_PER_BLOCK;
        cp16(sbase + (uint32_t)i * 16u, ps + i);
        cp16(sbase + (uint32_t)(CHUNK4 + i) * 16u, ls + i);
    }
}

__device__ __forceinline__ float cell_loss(const float* __restrict__ p,
                                           const float* __restrict__ l)
{
    const float s = 1.0f / (float)SIDE;
    float lconf = l[4];
    if (lconf == 0.0f) {
        // noobj: labels conf (indices 4 and 9) both zero here
        float d0 = p[4];
        float d1 = p[9];
        return 0.5f * (d0 * d0 + d1 * d1);
    }

    // 8B-aligned (cell stride 120 B): read via float2.
    const float2* p2 = (const float2*)p;
    const float2* l2 = (const float2*)l;

    float2 pa01 = p2[0], pa23 = p2[1], pa45 = p2[2], pa67 = p2[3], pa89 = p2[4];
    float2 la01 = l2[0], la23 = l2[1], la45 = l2[2], la67 = l2[3], la89 = l2[4];

    // IoU target: label box 0 only (lbox = lb[..., 0:1, :])
    float l1x = la01.x * s - 0.5f * la23.x;
    float l1y = la01.y * s - 0.5f * la23.y;
    float l2x = la01.x * s + 0.5f * la23.x;
    float l2y = la01.y * s + 0.5f * la23.y;
    float la  = la23.x * la23.y;

    // pred boxes: b0 = {pa01.x, pa01.y, pa23.x, pa23.y, pa45.x}
    //             b1 = {pa45.y, pa67.x, pa67.y, pa89.x, pa89.y}
    float bx[2] = { pa01.x, pa45.y };
    float by[2] = { pa01.y, pa67.x };
    float bw[2] = { pa23.x, pa67.y };
    float bh[2] = { pa23.y, pa89.x };
    float bc[2] = { pa45.x, pa89.y };

    // label boxes, same layout
    float lx[2] = { la01.x, la45.y };
    float ly[2] = { la01.y, la67.x };
    float lw[2] = { la23.x, la67.y };
    float lh[2] = { la23.y, la89.x };

    float iou[2];
    #pragma unroll
    for (int b = 0; b < 2; b++) {
        float p1x = bx[b] * s - 0.5f * bw[b];
        float p1y = by[b] * s - 0.5f * bh[b];
        float p2x = bx[b] * s + 0.5f * bw[b];
        float p2y = by[b] * s + 0.5f * bh[b];
        float iw = fmaxf(fminf(p2x, l2x) - fmaxf(p1x, l1x), 0.0f);
        float ih = fmaxf(fminf(p2y, l2y) - fmaxf(p1y, l1y), 0.0f);
        float inter = iw * ih;
        float pa = bw[b] * bh[b];
        iou[b] = inter / (pa + la - inter);
    }

    int idx = (iou[1] > iou[0]) ? 1 : 0;   // jnp.argmax: first max wins
    float maxiou = fmaxf(iou[0], iou[1]);

    float dresp = bc[idx] - maxiou;
    float resp  = dresp * dresp;

    float nrc = bc[1 - idx];
    float nr  = nrc * nrc;

    // responsible losses: pred box idx vs LABEL box idx (lr = take(lb))
    float dx = bx[idx] - lx[idx];
    float dy = by[idx] - ly[idx];
    float xy = dx * dx + dy * dy;

    float dw = sqrtf(bw[idx]) - sqrtf(lw[idx]);
    float dh = sqrtf(bh[idx]) - sqrtf(lh[idx]);
    float wh = dw * dw + dh * dh;

    float cls = 0.0f;
    #pragma unroll
    for (int j = 5; j < 15; j++) {
        float2 a = p2[j];
        float2 b = l2[j];
        float d0 = a.x - b.x;
        float d1 = a.y - b.y;
        cls += d0 * d0 + d1 * d1;
    }

    return 5.0f * (xy + wh) + 2.0f * resp + nr + cls;
}

extern __shared__ float4 smem4[];   // [2][1920] float4: buf x (preds|labels)

__global__ __launch_bounds__(CELLS_PER_BLOCK)
void yolo_pipe_kernel(const float* __restrict__ preds,
                      const float* __restrict__ labels,
                      float* __restrict__ out)
{
    const int t = threadIdx.x;
    const float4* p4 = (const float4*)preds;
    const float4* l4 = (const float4*)labels;

    const uint32_t sbase = (uint32_t)__cvta_generic_to_shared(smem4);

    float acc_cell = 0.0f;

    int c = blockIdx.x;
    int buf = 0;

    // Prologue: prefetch first chunk into buffer 0.
    prefetch_chunk(sbase, p4, l4, c, t);
    asm volatile("cp.async.commit_group;\n" ::: "memory");

    while (c < NUM_CHUNKS) {
        int cn = c + PGRID;
        if (cn < NUM_CHUNKS)
            prefetch_chunk(sbase + (uint32_t)(buf ^ 1) * BUF4 * 16u, p4, l4, cn, t);
        asm volatile("cp.async.commit_group;\n" ::: "memory");

        // All groups except the newest are done -> current buf ready.
        asm volatile("cp.async.wait_group 1;\n" ::: "memory");
        __syncthreads();

        const float* sp = (const float*)(smem4 + buf * BUF4);
        const float* sl = sp + CHUNKF;
        acc_cell += cell_loss(sp + t * FLOATS_PER_CELL, sl + t * FLOATS_PER_CELL);

        __syncthreads();   // all reads done before this buffer is refilled
        buf ^= 1;
        c = cn;
    }

    // Block reduction: warp shuffle tree then cross-warp via smem.
    float v = acc_cell;
    #pragma unroll
    for (int off = 16; off > 0; off >>= 1)
        v += __shfl_down_sync(0xFFFFFFFFu, v, off);

    __shared__ float wsum[CELLS_PER_BLOCK / 32];
    int lane = t & 31;
    int wid  = t >> 5;
    if (lane == 0) wsum[wid] = v;
    __syncthreads();

    __shared__ bool is_last;
    if (t == 0) {
        float bacc = 0.0f;
        #pragma unroll
        for (int w = 0; w < CELLS_PER_BLOCK / 32; w++) bacc += wsum[w];
        g_partials[blockIdx.x] = bacc;
        __threadfence();
        unsigned int ticket = atomicAdd(&g_ticket, 1u);
        is_last = (ticket == PGRID - 1);
    }
    __syncthreads();

    // Last-arriving block: deterministic final reduction over 444 partials.
    if (is_last) {
        double acc = 0.0;
        #pragma unroll 1
        for (int i = t; i < PGRID; i += CELLS_PER_BLOCK)
            acc += (double)g_partials[i];

        #pragma unroll
        for (int off = 16; off > 0; off >>= 1)
            acc += __shfl_down_sync(0xFFFFFFFFu, acc, off);

        __shared__ double dsum[CELLS_PER_BLOCK / 32];
        if (lane == 0) dsum[wid] = acc;
        __syncthreads();

        if (t == 0) {
            double total = 0.0;
            #pragma unroll
            for (int w = 0; w < CELLS_PER_BLOCK / 32; w++) total += dsum[w];
            out[0] = (float)(total / (double)NBATCH);
            g_ticket = 0;   // reset for next graph replay
        }
    }
}

extern "C" void kernel_launch(void* const* d_in, const int* in_sizes, int n_in,
                              void* d_out, int out_size)
{
    const float* preds  = (const float*)d_in[0];
    const float* labels = (const float*)d_in[1];
    float* out = (float*)d_out;

    static bool attr_set = false;
    if (!attr_set) {
        cudaFuncSetAttribute(yolo_pipe_kernel,
                             cudaFuncAttributeMaxDynamicSharedMemorySize,
                             SMEM_BYTES);
        attr_set = true;
    }

    yolo_pipe_kernel<<<PGRID, CELLS_PER_BLOCK, SMEM_BYTES>>>(preds, labels, out);
}

// round 11
// speedup vs baseline: 1.3979x; 1.0458x over previous
#include <cuda_runtime.h>
#include <cuda.h>
#include <math.h>
#include <stdint.h>

// YOLO loss: preds [16384,7,7,30] f32, labels same, scalar f32 out.
// R11 = R4 pipeline with 64-cell chunks for 7 CTAs/SM occupancy:
//   1036 blocks (148 SM x 7) x 128 threads; 12544 chunks of 64 cells.
//   smem 30720 B/CTA (2 stages x [64 cells preds | labels]).
//   cp.async.cg 16B double-buffer, wait_group 1. Threads 0..63 compute.
//   Block reduce + ticket atomic; last block reduces partials in double.

#define SIDE 7
#define NBATCH 16384
#define NTHREADS 128
#define TILE_CELLS 64
#define NUM_CHUNKS 12544           // 802816 / 64 exactly
#define PGRID 1036                 // 148 * 7 persistent blocks
#define FLOATS_PER_CELL 30
#define TILEF (TILE_CELLS * FLOATS_PER_CELL)   // 1920 floats
#define TILE4 (TILEF / 4)                      // 480 float4 per array
#define STAGE4 (2 * TILE4)                     // 960 float4 (preds|labels)
#define STAGE_BYTES (STAGE4 * 16)              // 15360 B
#define SMEM_BYTES (2 * STAGE_BYTES)           // 30720 B

__device__ float g_partials[PGRID];
__device__ unsigned int g_ticket = 0;

__device__ __forceinline__ void cp16(uint32_t smem_addr, const float4* gptr) {
    asm volatile("cp.async.cg.shared.global [%0], [%1], 16;\n"
                 :: "r"(smem_addr), "l"(gptr));
}

// Stage one chunk (480 float4 preds + 480 labels) into stage `sbase`.
__device__ __forceinline__ void prefetch_chunk(uint32_t sbase,
                                               const float4* __restrict__ p4,
                                               const float4* __restrict__ l4,
                                               int chunk, int t)
{
    const long long b = (long long)chunk * TILE4;
    const float4* ps = p4 + b;
    const float4* ls = l4 + b;
    #pragma unroll
    for (int j = 0; j < 3; j++) {             // 3*128 = 384
        int i = t + j * NTHREADS;
        cp16(sbase + (uint32_t)i * 16u, ps + i);
        cp16(sbase + (uint32_t)(TILE4 + i) * 16u, ls + i);
    }
    if (t < TILE4 - 3 * NTHREADS) {            // tail: 96 float4 each
        int i = t + 3 * NTHREADS;
        cp16(sbase + (uint32_t)i * 16u, ps + i);
        cp16(sbase + (uint32_t)(TILE4 + i) * 16u, ls + i);
    }
}

// R4's proven scalar cell loss (pointer-indexed smem reads).
__device__ __forceinline__ float cell_loss(const float* __restrict__ p,
                                           const float* __restrict__ l)
{
    const float s = 1.0f / (float)SIDE;
    float conf = l[4];
    if (conf == 0.0f) {
        float d0 = p[4] - l[4];
        float d1 = p[9] - l[9];
        return 0.5f * (d0 * d0 + d1 * d1);
    }
    float l1x = l[0] * s - 0.5f * l[2];
    float l1y = l[1] * s - 0.5f * l[3];
    float l2x = l[0] * s + 0.5f * l[2];
    float l2y = l[1] * s + 0.5f * l[3];
    float la  = l[2] * l[3];

    float iou0, iou1;
    #pragma unroll
    for (int b = 0; b < 2; b++) {
        const float* pb = p + b * 5;
        float p1x = pb[0] * s - 0.5f * pb[2];
        float p1y = pb[1] * s - 0.5f * pb[3];
        float p2x = pb[0] * s + 0.5f * pb[2];
        float p2y = pb[1] * s + 0.5f * pb[3];
        float iw = fmaxf(fminf(p2x, l2x) - fmaxf(p1x, l1x), 0.0f);
        float ih = fmaxf(fminf(p2y, l2y) - fmaxf(p1y, l1y), 0.0f);
        float inter = iw * ih;
        float pa = pb[2] * pb[3];
        float v = inter / (pa + la - inter);
        if (b == 0) iou0 = v; else iou1 = v;
    }

    int idx = (iou1 > iou0) ? 1 : 0;   // jnp.argmax: first max wins
    float maxiou = fmaxf(iou0, iou1);

    const float* pr = p + idx * 5;
    const float* lr = l + idx * 5;

    float dresp = pr[4] - maxiou;
    float resp  = dresp * dresp;

    float nrc = p[(1 - idx) * 5 + 4];
    float nr  = nrc * nrc;

    float dx = pr[0] - lr[0];
    float dy = pr[1] - lr[1];
    float xy = dx * dx + dy * dy;

    float dw = sqrtf(pr[2]) - sqrtf(lr[2]);
    float dh = sqrtf(pr[3]) - sqrtf(lr[3]);
    float wh = dw * dw + dh * dh;

    float cls = 0.0f;
    #pragma unroll
    for (int k = 10; k < 30; k++) {
        float d = p[k] - l[k];
        cls += d * d;
    }

    return 5.0f * (xy + wh) + 2.0f * resp + nr + cls;
}

extern __shared__ float4 smem4[];   // [2 stages][preds 480 | labels 480] float4

__global__ __launch_bounds__(NTHREADS)
void yolo_occ_pipe_kernel(const float* __restrict__ preds,
                          const float* __restrict__ labels,
                          float* __restrict__ out)
{
    const int t = threadIdx.x;
    const float4* p4 = (const float4*)preds;
    const float4* l4 = (const float4*)labels;

    const uint32_t sbase = (uint32_t)__cvta_generic_to_shared(smem4);

    float acc_cell = 0.0f;

    int c = blockIdx.x;
    int buf = 0;

    // Prologue: prefetch first chunk into stage 0.
    prefetch_chunk(sbase, p4, l4, c, t);
    asm volatile("cp.async.commit_group;\n" ::: "memory");

    while (c < NUM_CHUNKS) {
        int cn = c + PGRID;
        if (cn < NUM_CHUNKS)
            prefetch_chunk(sbase + (uint32_t)(buf ^ 1) * STAGE_BYTES, p4, l4, cn, t);
        asm volatile("cp.async.commit_group;\n" ::: "memory");

        // All groups except the newest are done -> current stage ready.
        asm volatile("cp.async.wait_group 1;\n" ::: "memory");
        __syncthreads();

        if (t < TILE_CELLS) {
            const float* sp = (const float*)(smem4 + (size_t)buf * STAGE4);
            const float* sl = sp + TILEF;
            acc_cell += cell_loss(sp + t * FLOATS_PER_CELL,
                                  sl + t * FLOATS_PER_CELL);
        }

        __syncthreads();   // all reads done before this stage is refilled
        buf ^= 1;
        c = cn;
    }

    // Block reduction: warp shuffle tree then cross-warp via smem.
    float v = acc_cell;
    #pragma unroll
    for (int off = 16; off > 0; off >>= 1)
        v += __shfl_down_sync(0xFFFFFFFFu, v, off);

    __shared__ float wsum[NTHREADS / 32];
    int lane = t & 31;
    int wid  = t >> 5;
    if (lane == 0) wsum[wid] = v;
    __syncthreads();

    __shared__ bool is_last;
    if (t == 0) {
        float bacc = 0.0f;
        #pragma unroll
        for (int w = 0; w < NTHREADS / 32; w++) bacc += wsum[w];
        g_partials[blockIdx.x] = bacc;
        __threadfence();
        unsigned int ticket = atomicAdd(&g_ticket, 1u);
        is_last = (ticket == PGRID - 1);
    }
    __syncthreads();

    // Last-arriving block: deterministic final reduction over 1036 partials.
    if (is_last) {
        double acc = 0.0;
        #pragma unroll 1
        for (int i = t; i < PGRID; i += NTHREADS)
            acc += (double)g_partials[i];

        #pragma unroll
        for (int off = 16; off > 0; off >>= 1)
            acc += __shfl_down_sync(0xFFFFFFFFu, acc, off);

        __shared__ double dsum[NTHREADS / 32];
        if (lane == 0) dsum[wid] = acc;
        __syncthreads();

        if (t == 0) {
            double total = 0.0;
            #pragma unroll
            for (int w = 0; w < NTHREADS / 32; w++) total += dsum[w];
            out[0] = (float)(total / (double)NBATCH);
            g_ticket = 0;   // reset for next graph replay
        }
    }
}

extern "C" void kernel_launch(void* const* d_in, const int* in_sizes, int n_in,
                              void* d_out, int out_size)
{
    const float* preds  = (const float*)d_in[0];
    const float* labels = (const float*)d_in[1];
    float* out = (float*)d_out;

    static bool attr_set = false;
    if (!attr_set) {
        cudaFuncSetAttribute(yolo_occ_pipe_kernel,
                             cudaFuncAttributeMaxDynamicSharedMemorySize,
                             SMEM_BYTES);
        attr_set = true;
    }

    yolo_occ_pipe_kernel<<<PGRID, NTHREADS, SMEM_BYTES>>>(preds, labels, out);
}